// round 4
// baseline (speedup 1.0000x reference)
#include <cuda_runtime.h>
#include <cuda_bf16.h>
#include <cstdint>

// ---------------------------------------------------------------------------
// Persistent-per-CTA causal generator, occupancy-2 version.
// Each CTA owns 64 batch rows and runs all 64 steps with X resident in smem.
// 256 threads = 8 warps: warp w -> rows [(w&3)*16, +16), col half (w>>2)*64.
// smem ~109 KB  =>  2 CTAs/SM  =>  4 warps/SMSP latency hiding.
//  - z streamed per step (256B) via cp.async double buffer (no resident zT)
//  - A_i single-buffered: consumed only by GEMM1, refilled during GEMM2/3
//  - H1/H2 aliased into one panel (extra barrier between read and overwrite)
// ---------------------------------------------------------------------------

#define XD 64
#define HD 128
#define BB 65536
#define BM 64
#define NT 256

// smem byte offsets. bf16 panels: rows of 64 bf16 (128B), SW128 swizzled.
#define OFF_X    0u         // X: [64][64]                        8192
#define OFF_A    8192u      // A_i: 2 N-panels [64][64]           16384
#define OFF_W1   24576u     // Ws1^T: 2 N-panels [128][64]        32768
#define OFF_W2   57344u     //                                    32768
#define OFF_H    90112u     // H: 2 K-panels [64][64]             16384
#define OFF_VEC  106496u    // 2 bufs x (Wz[128],bi[128],wf[128]) 3072
#define OFF_B1   109568u    // fp32[128]
#define OFF_B2   110080u
#define OFF_BF   110592u    // fp32[64]
#define OFF_ZC   110848u    // 2 bufs x fp32[64]
#define OFF_RED  111360u    // fp32[128]
#define SMEM_BYTES 111872u

__device__ __nv_bfloat16 g_A[XD * XD * HD];   // [step][k][n], mask folded in
__device__ __nv_bfloat16 g_W1[HD * HD];       // [k][n] = Ws1[n][k]
__device__ __nv_bfloat16 g_W2[HD * HD];       // [k][n] = Ws2[n][k]

__device__ __forceinline__ unsigned swz(unsigned off) {
    return off ^ ((off >> 3) & 0x70u);
}
__device__ __forceinline__ void ldsm4(unsigned addr, unsigned &r0, unsigned &r1,
                                      unsigned &r2, unsigned &r3) {
    asm volatile("ldmatrix.sync.aligned.m8n8.x4.shared.b16 {%0,%1,%2,%3}, [%4];"
                 : "=r"(r0), "=r"(r1), "=r"(r2), "=r"(r3) : "r"(addr));
}
__device__ __forceinline__ void ldsm4t(unsigned addr, unsigned &r0, unsigned &r1,
                                       unsigned &r2, unsigned &r3) {
    asm volatile("ldmatrix.sync.aligned.m8n8.x4.trans.shared.b16 {%0,%1,%2,%3}, [%4];"
                 : "=r"(r0), "=r"(r1), "=r"(r2), "=r"(r3) : "r"(addr));
}
__device__ __forceinline__ void mma16816(float *c, unsigned a0, unsigned a1,
                                         unsigned a2, unsigned a3,
                                         unsigned b0, unsigned b1) {
    asm volatile(
        "mma.sync.aligned.m16n8k16.row.col.f32.bf16.bf16.f32 "
        "{%0,%1,%2,%3}, {%4,%5,%6,%7}, {%8,%9}, {%0,%1,%2,%3};"
        : "+f"(c[0]), "+f"(c[1]), "+f"(c[2]), "+f"(c[3])
        : "r"(a0), "r"(a1), "r"(a2), "r"(a3), "r"(b0), "r"(b1));
}
__device__ __forceinline__ void cp16(unsigned saddr, const void *g) {
    asm volatile("cp.async.cg.shared.global [%0], [%1], 16;" ::"r"(saddr), "l"(g));
}
__device__ __forceinline__ void cp4(unsigned saddr, const void *g) {
    asm volatile("cp.async.ca.shared.global [%0], [%1], 4;" ::"r"(saddr), "l"(g));
}

// Warp computes a [16 rows x 64 cols] GEMM slice.
// A: row-major K-panels [64 rows][64 k] bf16 (panel stride aPanStride).
// B: one N-panel [K][64] bf16 at boff (rows = k).
template <int K16>
__device__ __forceinline__ void run_gemm(float acc[8][4], unsigned sbase,
                                         unsigned aoff, unsigned aPanStride,
                                         unsigned boff, int mb, int lane) {
    const unsigned half16 = (lane & 16) ? 16u : 0u;
    const unsigned klane  = (unsigned)(lane & 15);
    const unsigned arow   = (unsigned)(mb + (lane & 15));
#pragma unroll
    for (int kb = 0; kb < K16; kb++) {
        unsigned brow = (unsigned)kb * 16u + klane;
        unsigned b[16];
#pragma unroll
        for (int ntp = 0; ntp < 4; ntp++) {
            unsigned baddr = sbase + boff +
                             swz(brow * 128u + (unsigned)ntp * 32u + half16);
            ldsm4t(baddr, b[4 * ntp], b[4 * ntp + 1], b[4 * ntp + 2], b[4 * ntp + 3]);
        }
        unsigned a0, a1, a2, a3;
        unsigned aaddr = sbase + aoff + (unsigned)(kb >> 2) * aPanStride +
                         swz(arow * 128u + (unsigned)(kb & 3) * 32u + half16);
        ldsm4(aaddr, a0, a1, a2, a3);
#pragma unroll
        for (int ntp = 0; ntp < 4; ntp++) {
            mma16816(acc[2 * ntp],     a0, a1, a2, a3, b[4 * ntp], b[4 * ntp + 1]);
            mma16816(acc[2 * ntp + 1], a0, a1, a2, a3, b[4 * ntp + 2], b[4 * ntp + 3]);
        }
    }
}

__device__ __forceinline__ void zero_acc(float acc[8][4]) {
#pragma unroll
    for (int t = 0; t < 8; t++) {
        acc[t][0] = 0.f; acc[t][1] = 0.f; acc[t][2] = 0.f; acc[t][3] = 0.f;
    }
}

// Prefetch step j's A panel (single buffer), vectors and z column (double buf).
__device__ __forceinline__ void prefetch_step(int j, unsigned sbase, int tid,
                                              int R0, const float *Wi,
                                              const float *bi, const float *wf,
                                              const float *z) {
    const int b = j & 1;
    const char *gA = (const char *)g_A + (size_t)j * 16384;
#pragma unroll
    for (int c = tid; c < 1024; c += NT) {
        int row = c >> 4, nc = c & 15;
        unsigned off = (unsigned)(nc >> 3) * 8192u +
                       swz((unsigned)(row * 128 + (nc & 7) * 16));
        cp16(sbase + OFF_A + off, gA + c * 16);
    }
    unsigned vbase = sbase + OFF_VEC + (unsigned)b * 1536u;
    if (tid < 128) {
        cp4(vbase + tid * 4, Wi + ((size_t)j * HD + tid) * (XD + 1) + XD);
    } else if (tid < 160) {
        int t = tid - 128;
        cp16(vbase + 512 + t * 16, bi + j * HD + t * 4);
    } else if (tid < 192) {
        int t = tid - 160;
        cp16(vbase + 1024 + t * 16, wf + j * HD + t * 4);
    } else {
        int t = tid - 192;   // 64 threads: z column j for this CTA's rows
        cp4(sbase + OFF_ZC + (unsigned)b * 256u + t * 4,
            z + (size_t)(R0 + t) * XD + j);
    }
}

__global__ void __launch_bounds__(NT, 2)
gen_kernel(const float *__restrict__ x, const float *__restrict__ z,
           const float *__restrict__ Wi, const float *__restrict__ bi,
           const float *__restrict__ bs1, const float *__restrict__ bs2,
           const float *__restrict__ wf, const float *__restrict__ bfp,
           float *__restrict__ out) {
    extern __shared__ char smem[];
    const int tid  = threadIdx.x;
    const int lane = tid & 31;
    const int warp = tid >> 5;
    const int mb   = (warp & 3) * 16;   // 4 row groups of 16
    const int h    = warp >> 2;         // column half (0/1)
    const int R0   = blockIdx.x * BM;
    const unsigned sbase = (unsigned)__cvta_generic_to_shared(smem);

    float *sB1  = (float *)(smem + OFF_B1);
    float *sB2  = (float *)(smem + OFF_B2);
    float *sBF  = (float *)(smem + OFF_BF);
    float *sRed = (float *)(smem + OFF_RED);

    // ---------------- prologue: resident loads ----------------
    // X tile: x rows [R0, R0+64) x 64 cols, fp32 -> bf16 SW128
#pragma unroll
    for (int c = tid; c < BM * XD / 4; c += NT) {
        int row = c >> 4, f4 = c & 15;
        float4 v = *(const float4 *)(x + (size_t)(R0 + row) * XD + f4 * 4);
        __nv_bfloat162 p0 = __floats2bfloat162_rn(v.x, v.y);
        __nv_bfloat162 p1 = __floats2bfloat162_rn(v.z, v.w);
        unsigned off = swz((unsigned)(row * 128 + f4 * 8));
        uint2 u;
        u.x = *(unsigned *)&p0;
        u.y = *(unsigned *)&p1;
        *(uint2 *)(smem + OFF_X + off) = u;
    }
    // shared weights W1/W2 -> 2 N-panels each
    {
        const uint4 *gW1 = (const uint4 *)g_W1;
        const uint4 *gW2 = (const uint4 *)g_W2;
#pragma unroll
        for (int c = tid; c < 2048; c += NT) {
            int row = c >> 4, nc = c & 15;
            unsigned off = (unsigned)(nc >> 3) * 16384u +
                           swz((unsigned)(row * 128 + (nc & 7) * 16));
            *(uint4 *)(smem + OFF_W1 + off) = gW1[c];
            *(uint4 *)(smem + OFF_W2 + off) = gW2[c];
        }
    }
    if (tid < HD) {
        sB1[tid] = bs1[tid];
        sB2[tid] = bs2[tid];
        if (tid < XD) sBF[tid] = bfp[tid];
    }
    prefetch_step(0, sbase, tid, R0, Wi, bi, wf, z);
    asm volatile("cp.async.commit_group;" ::: "memory");

    float acc[8][4];
    const int r0 = mb + (lane >> 2), r1 = r0 + 8;

    // ---------------- 64 sequential steps ----------------
    for (int i = 0; i < XD; i++) {
        const int vb = i & 1;
        const float *sWz = (float *)(smem + OFF_VEC + vb * 1536u);
        const float *sBi = sWz + 128;
        const float *sWf = sWz + 256;
        const float *sZC = (float *)(smem + OFF_ZC + vb * 256u);

        asm volatile("cp.async.wait_group 0;" ::: "memory");
        __syncthreads();   // S0: A_i/vec_i/zc_i visible; X col i-1 visible

        // ---- GEMM1: h1 = relu(X @ A_i + z_i*Wz + bi) -> H ----
        zero_acc(acc);
        run_gemm<4>(acc, sbase, OFF_X, 8192u,
                    OFF_A + (unsigned)h * 8192u, mb, lane);
        {
            const float z0 = sZC[r0];
            const float z1 = sZC[r1];
#pragma unroll
            for (int nt = 0; nt < 8; nt++) {
                float *a = acc[nt];
                int cl = nt * 8 + 2 * (lane & 3);
                int c0 = h * 64 + cl;
                float wz0 = sWz[c0], wz1 = sWz[c0 + 1];
                float b0 = sBi[c0], b1 = sBi[c0 + 1];
                float v00 = fmaxf(fmaf(z0, wz0, a[0]) + b0, 0.f);
                float v01 = fmaxf(fmaf(z0, wz1, a[1]) + b1, 0.f);
                float v10 = fmaxf(fmaf(z1, wz0, a[2]) + b0, 0.f);
                float v11 = fmaxf(fmaf(z1, wz1, a[3]) + b1, 0.f);
                unsigned pbase = OFF_H + (unsigned)h * 8192u;
                unsigned coff  = (unsigned)(cl * 2);
                __nv_bfloat162 q0 = __floats2bfloat162_rn(v00, v01);
                __nv_bfloat162 q1 = __floats2bfloat162_rn(v10, v11);
                *(__nv_bfloat162 *)(smem + pbase + swz((unsigned)r0 * 128u + coff)) = q0;
                *(__nv_bfloat162 *)(smem + pbase + swz((unsigned)r1 * 128u + coff)) = q1;
            }
        }
        __syncthreads();   // S1: H=h1 ready; all warps done with A_i

        // overlap: refill A (single buffer) + next-step vectors/z
        if (i + 1 < XD) {
            prefetch_step(i + 1, sbase, tid, R0, Wi, bi, wf, z);
        }
        asm volatile("cp.async.commit_group;" ::: "memory");

        // ---- GEMM2: h2 = relu(h1 @ Ws1^T + bs1) ----
        zero_acc(acc);
        run_gemm<8>(acc, sbase, OFF_H, 8192u,
                    OFF_W1 + (unsigned)h * 16384u, mb, lane);
        __syncthreads();   // S2: all warps done READING h1 (H reused below)
        {
#pragma unroll
            for (int nt = 0; nt < 8; nt++) {
                float *a = acc[nt];
                int cl = nt * 8 + 2 * (lane & 3);
                int c0 = h * 64 + cl;
                float b0 = sB1[c0], b1 = sB1[c0 + 1];
                float v00 = fmaxf(a[0] + b0, 0.f);
                float v01 = fmaxf(a[1] + b1, 0.f);
                float v10 = fmaxf(a[2] + b0, 0.f);
                float v11 = fmaxf(a[3] + b1, 0.f);
                unsigned pbase = OFF_H + (unsigned)h * 8192u;
                unsigned coff  = (unsigned)(cl * 2);
                __nv_bfloat162 q0 = __floats2bfloat162_rn(v00, v01);
                __nv_bfloat162 q1 = __floats2bfloat162_rn(v10, v11);
                *(__nv_bfloat162 *)(smem + pbase + swz((unsigned)r0 * 128u + coff)) = q0;
                *(__nv_bfloat162 *)(smem + pbase + swz((unsigned)r1 * 128u + coff)) = q1;
            }
        }
        __syncthreads();   // S3: H=h2 ready

        // ---- GEMM3 + head ----
        zero_acc(acc);
        run_gemm<8>(acc, sbase, OFF_H, 8192u,
                    OFF_W2 + (unsigned)h * 16384u, mb, lane);
        {
            float p0 = 0.f, p1 = 0.f;
#pragma unroll
            for (int nt = 0; nt < 8; nt++) {
                float *a = acc[nt];
                int c0 = h * 64 + nt * 8 + 2 * (lane & 3);
                float b0 = sB2[c0], b1 = sB2[c0 + 1];
                float w0 = sWf[c0], w1 = sWf[c0 + 1];
                p0 += fmaxf(a[0] + b0, 0.f) * w0 + fmaxf(a[1] + b1, 0.f) * w1;
                p1 += fmaxf(a[2] + b0, 0.f) * w0 + fmaxf(a[3] + b1, 0.f) * w1;
            }
            p0 += __shfl_xor_sync(0xffffffffu, p0, 1);
            p0 += __shfl_xor_sync(0xffffffffu, p0, 2);
            p1 += __shfl_xor_sync(0xffffffffu, p1, 1);
            p1 += __shfl_xor_sync(0xffffffffu, p1, 2);
            if ((lane & 3) == 0) {
                sRed[h * BM + r0] = p0;
                sRed[h * BM + r1] = p1;
            }
        }
        __syncthreads();   // S4: sRed ready; all warps done reading H

        // combine halves, sigmoid, write X col i (bf16) + out col i (fp32)
        if (tid < BM) {
            float t = sRed[tid] + sRed[BM + tid] + sBF[i];
            float o = 1.f / (1.f + __expf(-t));
            out[(size_t)(R0 + tid) * XD + i] = o;
            *(__nv_bfloat16 *)(smem + OFF_X + swz((unsigned)(tid * 128 + i * 2))) =
                __float2bfloat16(o);
        }
        // top-of-loop S0 publishes the X update
    }
}

// ---- prep: fold adjacency mask into per-step bf16 input weights ----
__global__ void prep_A_kernel(const float *__restrict__ M, const float *__restrict__ Wi) {
    int idx = blockIdx.x * blockDim.x + threadIdx.x;
    if (idx >= XD * XD * HD) return;
    int i = idx >> 13;
    int k = (idx >> 7) & 63;
    int n = idx & 127;
    float v = (k == i) ? 0.f : M[k * XD + i] * Wi[((size_t)i * HD + n) * (XD + 1) + k];
    g_A[idx] = __float2bfloat16(v);
}

// ---- prep: transpose shared weights to [k][n] bf16 ----
__global__ void prep_W_kernel(const float *__restrict__ Ws1, const float *__restrict__ Ws2) {
    int idx = blockIdx.x * blockDim.x + threadIdx.x;
    if (idx >= HD * HD) return;
    int k = idx >> 7, n = idx & 127;
    g_W1[idx] = __float2bfloat16(Ws1[n * HD + k]);
    g_W2[idx] = __float2bfloat16(Ws2[n * HD + k]);
}

extern "C" void kernel_launch(void *const *d_in, const int *in_sizes, int n_in,
                              void *d_out, int out_size) {
    const float *x   = (const float *)d_in[0];
    const float *z   = (const float *)d_in[1];
    const float *M   = (const float *)d_in[2];
    const float *Wi  = (const float *)d_in[3];
    const float *bi  = (const float *)d_in[4];
    const float *Ws1 = (const float *)d_in[5];
    const float *bs1 = (const float *)d_in[6];
    const float *Ws2 = (const float *)d_in[7];
    const float *bs2 = (const float *)d_in[8];
    const float *wf  = (const float *)d_in[9];
    const float *bf  = (const float *)d_in[10];
    float *out = (float *)d_out;

    cudaFuncSetAttribute(gen_kernel, cudaFuncAttributeMaxDynamicSharedMemorySize,
                         (int)SMEM_BYTES);

    prep_A_kernel<<<(XD * XD * HD + 255) / 256, 256>>>(M, Wi);
    prep_W_kernel<<<(HD * HD + 255) / 256, 256>>>(Ws1, Ws2);
    gen_kernel<<<BB / BM, NT, SMEM_BYTES>>>(x, z, Wi, bi, bs1, bs2, wf, bf, out);
}

// round 5
// speedup vs baseline: 1.3211x; 1.3211x over previous
#include <cuda_runtime.h>
#include <cuda_bf16.h>
#include <cstdint>

// ---------------------------------------------------------------------------
// Persistent-per-CTA causal generator. R3 structure (proven 1219us) with
// GEMM2/GEMM3 switched to FP8 (e4m3) mma.sync m16n8k32.
//
// Fragment identity: m16n8k32.e4m3 A/B fragments == m16n8k16.bf16 fragments
// with each 16-bit element = (fp8[k], fp8[k+1]) pair along k. So panels,
// swizzle, and ldmatrix code are unchanged; only the MMA opcode changes.
//
// Scaling to avoid e4m3 subnormals: W1/W2 stored *32, h1/h2 stored *64.
// GEMM2: h2*64 = relu(acc/32 + bs1*64);  GEMM3: h3 = relu(acc/2048 + bs2).
// ---------------------------------------------------------------------------

#define XD 64
#define HD 128
#define BB 65536
#define BM 128
#define NT 256

#define SH 64.0f          // activation scale
#define INV2 (1.0f/32.0f)     // = SH / (SH*SW)
#define INV3 (1.0f/2048.0f)   // = 1 / (SH*SW)

// smem byte offsets. Panels: 128B rows, SW128 swizzled.
#define OFF_X    0u         // X bf16 [128][64]                  16384
#define OFF_A    16384u     // A_i bf16: 2 bufs x 2 halves       32768
#define OFF_W1   49152u     // W1 fp8-packed: 2 halves [64][128B]16384
#define OFF_W2   65536u     //                                   16384
#define OFF_H1   81920u     // h1 fp8 [128][128B]                16384
#define OFF_H2   98304u     //                                   16384
#define OFF_Z    114688u    // zT fp32 [64][132]                 33792
#define OFF_VEC  148480u    // 2 bufs x (Wz[128],bi[128],wf[128])3072
#define OFF_B1   151552u    // bs1*SH fp32[128]
#define OFF_B2   152064u    // bs2 fp32[128]
#define OFF_BF   152576u    // fp32[64]
#define OFF_RED  152832u    // fp32[256]
#define SMEM_BYTES 153856u

#define ZSTRIDE 132

__device__ __nv_bfloat16 g_A[XD * XD * HD];      // [step][k][n] bf16
__device__ unsigned short g_W1p[64 * HD];        // [kk][n] fp8 pairs, *32
__device__ unsigned short g_W2p[64 * HD];

__device__ __forceinline__ unsigned swz(unsigned off) {
    return off ^ ((off >> 3) & 0x70u);
}
__device__ __forceinline__ void ldsm4(unsigned addr, unsigned &r0, unsigned &r1,
                                      unsigned &r2, unsigned &r3) {
    asm volatile("ldmatrix.sync.aligned.m8n8.x4.shared.b16 {%0,%1,%2,%3}, [%4];"
                 : "=r"(r0), "=r"(r1), "=r"(r2), "=r"(r3) : "r"(addr));
}
__device__ __forceinline__ void ldsm4t(unsigned addr, unsigned &r0, unsigned &r1,
                                       unsigned &r2, unsigned &r3) {
    asm volatile("ldmatrix.sync.aligned.m8n8.x4.trans.shared.b16 {%0,%1,%2,%3}, [%4];"
                 : "=r"(r0), "=r"(r1), "=r"(r2), "=r"(r3) : "r"(addr));
}
__device__ __forceinline__ void mma_bf16(float *c, unsigned a0, unsigned a1,
                                         unsigned a2, unsigned a3,
                                         unsigned b0, unsigned b1) {
    asm volatile(
        "mma.sync.aligned.m16n8k16.row.col.f32.bf16.bf16.f32 "
        "{%0,%1,%2,%3}, {%4,%5,%6,%7}, {%8,%9}, {%0,%1,%2,%3};"
        : "+f"(c[0]), "+f"(c[1]), "+f"(c[2]), "+f"(c[3])
        : "r"(a0), "r"(a1), "r"(a2), "r"(a3), "r"(b0), "r"(b1));
}
__device__ __forceinline__ void mma_fp8(float *c, unsigned a0, unsigned a1,
                                        unsigned a2, unsigned a3,
                                        unsigned b0, unsigned b1) {
    asm volatile(
        "mma.sync.aligned.m16n8k32.row.col.f32.e4m3.e4m3.f32 "
        "{%0,%1,%2,%3}, {%4,%5,%6,%7}, {%8,%9}, {%0,%1,%2,%3};"
        : "+f"(c[0]), "+f"(c[1]), "+f"(c[2]), "+f"(c[3])
        : "r"(a0), "r"(a1), "r"(a2), "r"(a3), "r"(b0), "r"(b1));
}
// pack (lo=a, hi=b) floats into e4m3x2 (16-bit). cvt d, X, Y: X->upper, Y->lower.
__device__ __forceinline__ unsigned short f2e4m3x2(float lo, float hi) {
    unsigned short r;
    asm("cvt.rn.satfinite.e4m3x2.f32 %0, %1, %2;" : "=h"(r) : "f"(hi), "f"(lo));
    return r;
}
__device__ __forceinline__ void cp16(unsigned saddr, const void *g) {
    asm volatile("cp.async.cg.shared.global [%0], [%1], 16;" ::"r"(saddr), "l"(g));
}
__device__ __forceinline__ void cp4(unsigned saddr, const void *g) {
    asm volatile("cp.async.ca.shared.global [%0], [%1], 4;" ::"r"(saddr), "l"(g));
}

// Warp computes a [32 rows x 64 cols] GEMM slice. Same geometry for bf16-k16
// blocks and fp8-k32 blocks (16 rows of 16-bit units per block either way).
// A: row-major [rows][128B], panel per 4 kb (stride unused when KB<=4).
// B: one N-panel [16*KB rows][128B] at boff.
template <int KB, bool FP8>
__device__ __forceinline__ void run_gemm(float acc[16][4], unsigned sbase,
                                         unsigned aoff, unsigned boff,
                                         int mb, int lane) {
    const unsigned half16 = (lane & 16) ? 16u : 0u;
    const unsigned klane  = (unsigned)(lane & 15);
#pragma unroll
    for (int kb = 0; kb < KB; kb++) {
        unsigned brow = (unsigned)kb * 16u + klane;
        unsigned b[16];
#pragma unroll
        for (int ntp = 0; ntp < 4; ntp++) {
            unsigned baddr = sbase + boff +
                             swz(brow * 128u + (unsigned)ntp * 32u + half16);
            ldsm4t(baddr, b[4 * ntp], b[4 * ntp + 1], b[4 * ntp + 2], b[4 * ntp + 3]);
        }
#pragma unroll
        for (int mt = 0; mt < 2; mt++) {
            unsigned arow = (unsigned)(mb + mt * 16 + (lane & 15));
            unsigned a0, a1, a2, a3;
            unsigned aaddr = sbase + aoff +
                             swz(arow * 128u + (unsigned)(kb & 3) * 32u + half16);
            ldsm4(aaddr, a0, a1, a2, a3);
#pragma unroll
            for (int ntp = 0; ntp < 4; ntp++) {
                if (FP8) {
                    mma_fp8(acc[mt * 8 + 2 * ntp], a0, a1, a2, a3,
                            b[4 * ntp], b[4 * ntp + 1]);
                    mma_fp8(acc[mt * 8 + 2 * ntp + 1], a0, a1, a2, a3,
                            b[4 * ntp + 2], b[4 * ntp + 3]);
                } else {
                    mma_bf16(acc[mt * 8 + 2 * ntp], a0, a1, a2, a3,
                             b[4 * ntp], b[4 * ntp + 1]);
                    mma_bf16(acc[mt * 8 + 2 * ntp + 1], a0, a1, a2, a3,
                             b[4 * ntp + 2], b[4 * ntp + 3]);
                }
            }
        }
    }
}

__device__ __forceinline__ void zero_acc(float acc[16][4]) {
#pragma unroll
    for (int t = 0; t < 16; t++) {
        acc[t][0] = 0.f; acc[t][1] = 0.f; acc[t][2] = 0.f; acc[t][3] = 0.f;
    }
}

__device__ __forceinline__ void prefetch_step(int j, unsigned sbase, int tid,
                                              const float *Wi, const float *bi,
                                              const float *wf) {
    const int b = j & 1;
    unsigned abase = sbase + OFF_A + (unsigned)b * 16384u;
    const char *gA = (const char *)g_A + (size_t)j * 16384;
#pragma unroll
    for (int c = tid; c < 1024; c += NT) {
        int row = c >> 4, nc = c & 15;
        unsigned off = (unsigned)(nc >> 3) * 8192u +
                       swz((unsigned)(row * 128 + (nc & 7) * 16));
        cp16(abase + off, gA + c * 16);
    }
    unsigned vbase = sbase + OFF_VEC + (unsigned)b * 1536u;
    if (tid < 128) {
        cp4(vbase + tid * 4, Wi + ((size_t)j * HD + tid) * (XD + 1) + XD);
    } else if (tid < 160) {
        int t = tid - 128;
        cp16(vbase + 512 + t * 16, bi + j * HD + t * 4);
    } else if (tid < 192) {
        int t = tid - 160;
        cp16(vbase + 1024 + t * 16, wf + j * HD + t * 4);
    }
}

__global__ void __launch_bounds__(NT, 1)
gen_kernel(const float *__restrict__ x, const float *__restrict__ z,
           const float *__restrict__ Wi, const float *__restrict__ bi,
           const float *__restrict__ bs1, const float *__restrict__ bs2,
           const float *__restrict__ wf, const float *__restrict__ bfp,
           float *__restrict__ out) {
    extern __shared__ char smem[];
    const int tid  = threadIdx.x;
    const int lane = tid & 31;
    const int warp = tid >> 5;
    const int mb   = (warp & 3) * 32;   // 4 row groups of 32
    const int h    = warp >> 2;         // column half (0/1)
    const int R0   = blockIdx.x * BM;
    const unsigned sbase = (unsigned)__cvta_generic_to_shared(smem);

    float *sZT  = (float *)(smem + OFF_Z);
    float *sB1  = (float *)(smem + OFF_B1);
    float *sB2  = (float *)(smem + OFF_B2);
    float *sBF  = (float *)(smem + OFF_BF);
    float *sRed = (float *)(smem + OFF_RED);

    // ---------------- prologue: resident loads ----------------
    // X tile: rows [R0, R0+128) x 64 cols, fp32 -> bf16 SW128
#pragma unroll
    for (int c = tid; c < BM * XD / 4; c += NT) {
        int row = c >> 4, f4 = c & 15;
        float4 v = *(const float4 *)(x + (size_t)(R0 + row) * XD + f4 * 4);
        __nv_bfloat162 p0 = __floats2bfloat162_rn(v.x, v.y);
        __nv_bfloat162 p1 = __floats2bfloat162_rn(v.z, v.w);
        unsigned off = swz((unsigned)(row * 128 + f4 * 8));
        uint2 u;
        u.x = *(unsigned *)&p0;
        u.y = *(unsigned *)&p1;
        *(uint2 *)(smem + OFF_X + off) = u;
    }
    // zT resident
#pragma unroll
    for (int idx = tid; idx < BM * XD; idx += NT) {
        int row = idx >> 6, c = idx & 63;
        sZT[c * ZSTRIDE + row] = z[(size_t)(R0 + row) * XD + c];
    }
    // W1/W2 fp8 panels: g_W*p is [64 kk rows][256B]; split into 2 N-halves
    {
        const uint4 *gW1 = (const uint4 *)g_W1p;
        const uint4 *gW2 = (const uint4 *)g_W2p;
#pragma unroll
        for (int c = tid; c < 1024; c += NT) {
            int row = c >> 4, nc = c & 15;
            unsigned off = (unsigned)(nc >> 3) * 8192u +
                           swz((unsigned)(row * 128 + (nc & 7) * 16));
            *(uint4 *)(smem + OFF_W1 + off) = gW1[c];
            *(uint4 *)(smem + OFF_W2 + off) = gW2[c];
        }
    }
    if (tid < HD) {
        sB1[tid] = bs1[tid] * SH;    // pre-scaled for GEMM2 epilogue
        sB2[tid] = bs2[tid];
        if (tid < XD) sBF[tid] = bfp[tid];
    }
    prefetch_step(0, sbase, tid, Wi, bi, wf);
    asm volatile("cp.async.commit_group;" ::: "memory");

    float acc[16][4];

    // ---------------- 64 sequential steps ----------------
    for (int i = 0; i < XD; i++) {
        const int vb = i & 1;
        const float *sWz = (float *)(smem + OFF_VEC + vb * 1536u);
        const float *sBi = sWz + 128;
        const float *sWf = sWz + 256;

        asm volatile("cp.async.wait_group 0;" ::: "memory");
        __syncthreads();   // A_i/vec_i visible; X col i-1 visible

        // ---- GEMM1 (bf16): h1 = relu(X @ A_i + z_i*Wz + bi), store *SH fp8 ----
        zero_acc(acc);
        run_gemm<4, false>(acc, sbase, OFF_X,
                           OFF_A + (unsigned)vb * 16384u + (unsigned)h * 8192u,
                           mb, lane);
        if (i + 1 < XD) prefetch_step(i + 1, sbase, tid, Wi, bi, wf);
        asm volatile("cp.async.commit_group;" ::: "memory");
#pragma unroll
        for (int mt = 0; mt < 2; mt++) {
            const int r0 = mb + mt * 16 + (lane >> 2), r1 = r0 + 8;
            const float z0 = sZT[i * ZSTRIDE + r0];
            const float z1 = sZT[i * ZSTRIDE + r1];
#pragma unroll
            for (int nt = 0; nt < 8; nt++) {
                float *a = acc[mt * 8 + nt];
                int cl = nt * 8 + 2 * (lane & 3);
                int c0 = h * 64 + cl;
                float wz0 = sWz[c0], wz1 = sWz[c0 + 1];
                float b0 = sBi[c0], b1 = sBi[c0 + 1];
                float v00 = fmaxf(fmaf(z0, wz0, a[0]) + b0, 0.f) * SH;
                float v01 = fmaxf(fmaf(z0, wz1, a[1]) + b1, 0.f) * SH;
                float v10 = fmaxf(fmaf(z1, wz0, a[2]) + b0, 0.f) * SH;
                float v11 = fmaxf(fmaf(z1, wz1, a[3]) + b1, 0.f) * SH;
                *(unsigned short *)(smem + OFF_H1 + swz((unsigned)(r0 * 128 + c0))) =
                    f2e4m3x2(v00, v01);
                *(unsigned short *)(smem + OFF_H1 + swz((unsigned)(r1 * 128 + c0))) =
                    f2e4m3x2(v10, v11);
            }
        }
        __syncthreads();

        // ---- GEMM2 (fp8): h2*SH = relu(acc/32 + bs1*SH) ----
        zero_acc(acc);
        run_gemm<4, true>(acc, sbase, OFF_H1, OFF_W1 + (unsigned)h * 8192u,
                          mb, lane);
#pragma unroll
        for (int mt = 0; mt < 2; mt++) {
            const int r0 = mb + mt * 16 + (lane >> 2), r1 = r0 + 8;
#pragma unroll
            for (int nt = 0; nt < 8; nt++) {
                float *a = acc[mt * 8 + nt];
                int cl = nt * 8 + 2 * (lane & 3);
                int c0 = h * 64 + cl;
                float b0 = sB1[c0], b1 = sB1[c0 + 1];
                float v00 = fmaxf(fmaf(a[0], INV2, b0), 0.f);
                float v01 = fmaxf(fmaf(a[1], INV2, b1), 0.f);
                float v10 = fmaxf(fmaf(a[2], INV2, b0), 0.f);
                float v11 = fmaxf(fmaf(a[3], INV2, b1), 0.f);
                *(unsigned short *)(smem + OFF_H2 + swz((unsigned)(r0 * 128 + c0))) =
                    f2e4m3x2(v00, v01);
                *(unsigned short *)(smem + OFF_H2 + swz((unsigned)(r1 * 128 + c0))) =
                    f2e4m3x2(v10, v11);
            }
        }
        __syncthreads();

        // ---- GEMM3 (fp8) + head: h3 = relu(acc/2048 + bs2); p = h3 . wf ----
        zero_acc(acc);
        run_gemm<4, true>(acc, sbase, OFF_H2, OFF_W2 + (unsigned)h * 8192u,
                          mb, lane);
#pragma unroll
        for (int mt = 0; mt < 2; mt++) {
            const int r0 = mb + mt * 16 + (lane >> 2), r1 = r0 + 8;
            float p0 = 0.f, p1 = 0.f;
#pragma unroll
            for (int nt = 0; nt < 8; nt++) {
                float *a = acc[mt * 8 + nt];
                int c0 = h * 64 + nt * 8 + 2 * (lane & 3);
                float b0 = sB2[c0], b1 = sB2[c0 + 1];
                float w0 = sWf[c0], w1 = sWf[c0 + 1];
                p0 += fmaxf(fmaf(a[0], INV3, b0), 0.f) * w0 +
                      fmaxf(fmaf(a[1], INV3, b1), 0.f) * w1;
                p1 += fmaxf(fmaf(a[2], INV3, b0), 0.f) * w0 +
                      fmaxf(fmaf(a[3], INV3, b1), 0.f) * w1;
            }
            p0 += __shfl_xor_sync(0xffffffffu, p0, 1);
            p0 += __shfl_xor_sync(0xffffffffu, p0, 2);
            p1 += __shfl_xor_sync(0xffffffffu, p1, 1);
            p1 += __shfl_xor_sync(0xffffffffu, p1, 2);
            if ((lane & 3) == 0) {
                sRed[h * BM + r0] = p0;
                sRed[h * BM + r1] = p1;
            }
        }
        __syncthreads();

        // combine halves, sigmoid, write X col i (bf16) + out col i (fp32)
        if (tid < BM) {
            float t = sRed[tid] + sRed[BM + tid] + sBF[i];
            float o = 1.f / (1.f + __expf(-t));
            out[(size_t)(R0 + tid) * XD + i] = o;
            *(__nv_bfloat16 *)(smem + OFF_X + swz((unsigned)(tid * 128 + i * 2))) =
                __float2bfloat16(o);
        }
        // top-of-loop sync publishes the X update
    }
}

// ---- prep: fold adjacency mask into per-step bf16 input weights ----
__global__ void prep_A_kernel(const float *__restrict__ M, const float *__restrict__ Wi) {
    int idx = blockIdx.x * blockDim.x + threadIdx.x;
    if (idx >= XD * XD * HD) return;
    int i = idx >> 13;
    int k = (idx >> 7) & 63;
    int n = idx & 127;
    float v = (k == i) ? 0.f : M[k * XD + i] * Wi[((size_t)i * HD + n) * (XD + 1) + k];
    g_A[idx] = __float2bfloat16(v);
}

// ---- prep: shared weights -> fp8 pairs [kk][n], scaled *32 ----
__global__ void prep_W_kernel(const float *__restrict__ Ws1, const float *__restrict__ Ws2) {
    int idx = blockIdx.x * blockDim.x + threadIdx.x;
    if (idx >= 64 * HD) return;
    int kk = idx >> 7, n = idx & 127;
    float l1 = Ws1[n * HD + 2 * kk] * 32.f;
    float h1v = Ws1[n * HD + 2 * kk + 1] * 32.f;
    float l2 = Ws2[n * HD + 2 * kk] * 32.f;
    float h2v = Ws2[n * HD + 2 * kk + 1] * 32.f;
    g_W1p[idx] = f2e4m3x2(l1, h1v);
    g_W2p[idx] = f2e4m3x2(l2, h2v);
}

extern "C" void kernel_launch(void *const *d_in, const int *in_sizes, int n_in,
                              void *d_out, int out_size) {
    const float *x   = (const float *)d_in[0];
    const float *z   = (const float *)d_in[1];
    const float *M   = (const float *)d_in[2];
    const float *Wi  = (const float *)d_in[3];
    const float *bi  = (const float *)d_in[4];
    const float *Ws1 = (const float *)d_in[5];
    const float *bs1 = (const float *)d_in[6];
    const float *Ws2 = (const float *)d_in[7];
    const float *bs2 = (const float *)d_in[8];
    const float *wf  = (const float *)d_in[9];
    const float *bf  = (const float *)d_in[10];
    float *out = (float *)d_out;

    cudaFuncSetAttribute(gen_kernel, cudaFuncAttributeMaxDynamicSharedMemorySize,
                         (int)SMEM_BYTES);

    prep_A_kernel<<<(XD * XD * HD + 255) / 256, 256>>>(M, Wi);
    prep_W_kernel<<<(64 * HD + 255) / 256, 256>>>(Ws1, Ws2);
    gen_kernel<<<BB / BM, NT, SMEM_BYTES>>>(x, z, Wi, bi, bs1, bs2, wf, bf, out);
}

// round 7
// speedup vs baseline: 1.7005x; 1.2872x over previous
#include <cuda_runtime.h>
#include <cuda_bf16.h>
#include <cstdint>

// ---------------------------------------------------------------------------
// Persistent-per-CTA causal generator, register-chained GEMMs.
//
// Fragment identity: the m16n8 C-fragment (c0,c1 @ row=lane>>2,col=2*(lane&3);
// c2,c3 @ row+8) matches the m16n8k16 A-fragment layout. Two adjacent n8
// C-tiles, packed as bf16x2, form one k16 A-fragment. So each warp keeps its
// 16 rows x 128 cols of h1/h2 entirely in registers: no H smem panels, no
// inter-GEMM barriers. One __syncthreads per step (X column publish).
//
// 8 warps x 16 rows = 128 batch rows per CTA; X resident in smem; A_i
// double-buffered via cp.async, prefetched across the whole step.
// ---------------------------------------------------------------------------

#define XD 64
#define HD 128
#define BB 65536
#define BM 128
#define NT 256

// smem byte offsets. bf16 panels: 128B rows, SW128 swizzled.
#define OFF_X    0u         // X bf16 [128][64]                   16384
#define OFF_A    16384u     // A_i: 2 bufs x 2 panels [64][64]    32768
#define OFF_W1   49152u     // Ws1^T: 2 N-panels [128][64]        32768
#define OFF_W2   81920u     //                                    32768
#define OFF_Z    114688u    // zT fp32 [64][132]                  33792
#define OFF_VEC  148480u    // 2 bufs x (Wz[128],bi[128],wf[128]) 3072
#define OFF_B1   151552u    // fp32[128]
#define OFF_B2   152064u    // fp32[128]
#define OFF_BF   152576u    // fp32[64]
#define SMEM_BYTES 152832u

#define ZSTRIDE 132

__device__ __nv_bfloat16 g_A[XD * XD * HD];   // [step][k][n], mask folded in
__device__ __nv_bfloat16 g_W1[HD * HD];       // [k][n] = Ws1[n][k]
__device__ __nv_bfloat16 g_W2[HD * HD];       // [k][n] = Ws2[n][k]

__device__ __forceinline__ unsigned swz(unsigned off) {
    return off ^ ((off >> 3) & 0x70u);
}
__device__ __forceinline__ void ldsm4(unsigned addr, unsigned &r0, unsigned &r1,
                                      unsigned &r2, unsigned &r3) {
    asm volatile("ldmatrix.sync.aligned.m8n8.x4.shared.b16 {%0,%1,%2,%3}, [%4];"
                 : "=r"(r0), "=r"(r1), "=r"(r2), "=r"(r3) : "r"(addr));
}
__device__ __forceinline__ void ldsm4t(unsigned addr, unsigned &r0, unsigned &r1,
                                       unsigned &r2, unsigned &r3) {
    asm volatile("ldmatrix.sync.aligned.m8n8.x4.trans.shared.b16 {%0,%1,%2,%3}, [%4];"
                 : "=r"(r0), "=r"(r1), "=r"(r2), "=r"(r3) : "r"(addr));
}
__device__ __forceinline__ void mma16816(float *c, unsigned a0, unsigned a1,
                                         unsigned a2, unsigned a3,
                                         unsigned b0, unsigned b1) {
    asm volatile(
        "mma.sync.aligned.m16n8k16.row.col.f32.bf16.bf16.f32 "
        "{%0,%1,%2,%3}, {%4,%5,%6,%7}, {%8,%9}, {%0,%1,%2,%3};"
        : "+f"(c[0]), "+f"(c[1]), "+f"(c[2]), "+f"(c[3])
        : "r"(a0), "r"(a1), "r"(a2), "r"(a3), "r"(b0), "r"(b1));
}
__device__ __forceinline__ unsigned packbf(float lo, float hi) {
    __nv_bfloat162 t = __floats2bfloat162_rn(lo, hi);
    return *(unsigned *)&t;
}
__device__ __forceinline__ void cp16(unsigned saddr, const void *g) {
    asm volatile("cp.async.cg.shared.global [%0], [%1], 16;" ::"r"(saddr), "l"(g));
}
__device__ __forceinline__ void cp4(unsigned saddr, const void *g) {
    asm volatile("cp.async.ca.shared.global [%0], [%1], 4;" ::"r"(saddr), "l"(g));
}

__device__ __forceinline__ void zero_acc(float acc[16][4]) {
#pragma unroll
    for (int t = 0; t < 16; t++) {
        acc[t][0] = 0.f; acc[t][1] = 0.f; acc[t][2] = 0.f; acc[t][3] = 0.f;
    }
}

__device__ __forceinline__ void prefetch_step(int j, unsigned sbase, int tid,
                                              const float *Wi, const float *bi,
                                              const float *wf) {
    const int b = j & 1;
    unsigned abase = sbase + OFF_A + (unsigned)b * 16384u;
    const char *gA = (const char *)g_A + (size_t)j * 16384;
#pragma unroll
    for (int c = tid; c < 1024; c += NT) {
        int row = c >> 4, nc = c & 15;
        unsigned off = (unsigned)(nc >> 3) * 8192u +
                       swz((unsigned)(row * 128 + (nc & 7) * 16));
        cp16(abase + off, gA + c * 16);
    }
    unsigned vbase = sbase + OFF_VEC + (unsigned)b * 1536u;
    if (tid < 128) {
        cp4(vbase + tid * 4, Wi + ((size_t)j * HD + tid) * (XD + 1) + XD);
    } else if (tid < 160) {
        int t = tid - 128;
        cp16(vbase + 512 + t * 16, bi + j * HD + t * 4);
    } else if (tid < 192) {
        int t = tid - 160;
        cp16(vbase + 1024 + t * 16, wf + j * HD + t * 4);
    }
}

__global__ void __launch_bounds__(NT, 1)
gen_kernel(const float *__restrict__ x, const float *__restrict__ z,
           const float *__restrict__ Wi, const float *__restrict__ bi,
           const float *__restrict__ bs1, const float *__restrict__ bs2,
           const float *__restrict__ wf, const float *__restrict__ bfp,
           float *__restrict__ out) {
    extern __shared__ char smem[];
    const int tid  = threadIdx.x;
    const int lane = tid & 31;
    const int warp = tid >> 5;
    const int mb   = warp * 16;        // 8 warps x 16 rows = 128 rows
    const int R0   = blockIdx.x * BM;
    const unsigned sbase  = (unsigned)__cvta_generic_to_shared(smem);
    const unsigned half16 = (lane & 16) ? 16u : 0u;
    const unsigned klane  = (unsigned)(lane & 15);
    const unsigned arow   = (unsigned)(mb + (lane & 15));

    float *sZT = (float *)(smem + OFF_Z);
    float *sB1 = (float *)(smem + OFF_B1);
    float *sB2 = (float *)(smem + OFF_B2);
    float *sBF = (float *)(smem + OFF_BF);

    // ---------------- prologue: resident loads ----------------
#pragma unroll
    for (int c = tid; c < BM * XD / 4; c += NT) {
        int row = c >> 4, f4 = c & 15;
        float4 v = *(const float4 *)(x + (size_t)(R0 + row) * XD + f4 * 4);
        __nv_bfloat162 p0 = __floats2bfloat162_rn(v.x, v.y);
        __nv_bfloat162 p1 = __floats2bfloat162_rn(v.z, v.w);
        unsigned off = swz((unsigned)(row * 128 + f4 * 8));
        uint2 u;
        u.x = *(unsigned *)&p0;
        u.y = *(unsigned *)&p1;
        *(uint2 *)(smem + OFF_X + off) = u;
    }
#pragma unroll
    for (int idx = tid; idx < BM * XD; idx += NT) {
        int row = idx >> 6, c = idx & 63;
        sZT[c * ZSTRIDE + row] = z[(size_t)(R0 + row) * XD + c];
    }
    {
        const uint4 *gW1 = (const uint4 *)g_W1;
        const uint4 *gW2 = (const uint4 *)g_W2;
#pragma unroll
        for (int c = tid; c < 2048; c += NT) {
            int row = c >> 4, nc = c & 15;
            unsigned off = (unsigned)(nc >> 3) * 16384u +
                           swz((unsigned)(row * 128 + (nc & 7) * 16));
            *(uint4 *)(smem + OFF_W1 + off) = gW1[c];
            *(uint4 *)(smem + OFF_W2 + off) = gW2[c];
        }
    }
    if (tid < HD) {
        sB1[tid] = bs1[tid];
        sB2[tid] = bs2[tid];
        if (tid < XD) sBF[tid] = bfp[tid];
    }
    prefetch_step(0, sbase, tid, Wi, bi, wf);
    asm volatile("cp.async.commit_group;" ::: "memory");

    float acc[16][4];
    unsigned af[8][4];   // A-fragments for the next GEMM (k=16 blocks)
    const int r0 = mb + (lane >> 2), r1 = r0 + 8;

    // ---------------- 64 sequential steps, ONE barrier each ----------------
    for (int i = 0; i < XD; i++) {
        const int vb = i & 1;
        const float *sWz = (float *)(smem + OFF_VEC + vb * 1536u);
        const float *sBi = sWz + 128;
        const float *sWf = sWz + 256;

        asm volatile("cp.async.wait_group 0;" ::: "memory");
        __syncthreads();   // A_i/vec_i visible; X col i-1 visible

        // prefetch step i+1 into the other buffer (free since step i-1)
        if (i + 1 < XD) prefetch_step(i + 1, sbase, tid, Wi, bi, wf);
        asm volatile("cp.async.commit_group;" ::: "memory");

        // ---- GEMM1: [16x128] = X[16x64] @ A_i[64x128] ----
        zero_acc(acc);
#pragma unroll
        for (int kb = 0; kb < 4; kb++) {
            unsigned a0, a1, a2, a3;
            unsigned aaddr = sbase + OFF_X +
                             swz(arow * 128u + (unsigned)kb * 32u + half16);
            ldsm4(aaddr, a0, a1, a2, a3);
            unsigned brow = (unsigned)kb * 16u + klane;
            unsigned bbase = sbase + OFF_A + (unsigned)vb * 16384u;
#pragma unroll
            for (int ntp = 0; ntp < 8; ntp++) {
                unsigned b0, b1, b2, b3;
                unsigned baddr = bbase + (unsigned)(ntp >> 2) * 8192u +
                                 swz(brow * 128u + (unsigned)(ntp & 3) * 32u + half16);
                ldsm4t(baddr, b0, b1, b2, b3);
                mma16816(acc[2 * ntp],     a0, a1, a2, a3, b0, b1);
                mma16816(acc[2 * ntp + 1], a0, a1, a2, a3, b2, b3);
            }
        }
        // epilogue 1: relu(acc + z*Wz + bi) -> A-fragments (registers)
        {
            const float z0 = sZT[i * ZSTRIDE + r0];
            const float z1 = sZT[i * ZSTRIDE + r1];
#pragma unroll
            for (int kb = 0; kb < 8; kb++) {
#pragma unroll
                for (int t = 0; t < 2; t++) {
                    float *a = acc[2 * kb + t];
                    int c0 = (2 * kb + t) * 8 + 2 * (lane & 3);
                    float wz0 = sWz[c0], wz1 = sWz[c0 + 1];
                    float b0 = sBi[c0], b1 = sBi[c0 + 1];
                    float v00 = fmaxf(fmaf(z0, wz0, a[0]) + b0, 0.f);
                    float v01 = fmaxf(fmaf(z0, wz1, a[1]) + b1, 0.f);
                    float v10 = fmaxf(fmaf(z1, wz0, a[2]) + b0, 0.f);
                    float v11 = fmaxf(fmaf(z1, wz1, a[3]) + b1, 0.f);
                    af[kb][2 * t]     = packbf(v00, v01);
                    af[kb][2 * t + 1] = packbf(v10, v11);
                }
            }
        }

        // ---- GEMM2: [16x128] = h1(regs) @ Ws1^T(smem) ----
        zero_acc(acc);
#pragma unroll
        for (int kb = 0; kb < 8; kb++) {
            unsigned brow = (unsigned)kb * 16u + klane;
#pragma unroll
            for (int ntp = 0; ntp < 8; ntp++) {
                unsigned b0, b1, b2, b3;
                unsigned baddr = sbase + OFF_W1 + (unsigned)(ntp >> 2) * 16384u +
                                 swz(brow * 128u + (unsigned)(ntp & 3) * 32u + half16);
                ldsm4t(baddr, b0, b1, b2, b3);
                mma16816(acc[2 * ntp],     af[kb][0], af[kb][1], af[kb][2], af[kb][3], b0, b1);
                mma16816(acc[2 * ntp + 1], af[kb][0], af[kb][1], af[kb][2], af[kb][3], b2, b3);
            }
        }
        // epilogue 2: relu(acc + bs1) -> A-fragments
#pragma unroll
        for (int kb = 0; kb < 8; kb++) {
#pragma unroll
            for (int t = 0; t < 2; t++) {
                float *a = acc[2 * kb + t];
                int c0 = (2 * kb + t) * 8 + 2 * (lane & 3);
                float b0 = sB1[c0], b1 = sB1[c0 + 1];
                float v00 = fmaxf(a[0] + b0, 0.f);
                float v01 = fmaxf(a[1] + b1, 0.f);
                float v10 = fmaxf(a[2] + b0, 0.f);
                float v11 = fmaxf(a[3] + b1, 0.f);
                af[kb][2 * t]     = packbf(v00, v01);
                af[kb][2 * t + 1] = packbf(v10, v11);
            }
        }

        // ---- GEMM3: [16x128] = h2(regs) @ Ws2^T(smem) ----
        zero_acc(acc);
#pragma unroll
        for (int kb = 0; kb < 8; kb++) {
            unsigned brow = (unsigned)kb * 16u + klane;
#pragma unroll
            for (int ntp = 0; ntp < 8; ntp++) {
                unsigned b0, b1, b2, b3;
                unsigned baddr = sbase + OFF_W2 + (unsigned)(ntp >> 2) * 16384u +
                                 swz(brow * 128u + (unsigned)(ntp & 3) * 32u + half16);
                ldsm4t(baddr, b0, b1, b2, b3);
                mma16816(acc[2 * ntp],     af[kb][0], af[kb][1], af[kb][2], af[kb][3], b0, b1);
                mma16816(acc[2 * ntp + 1], af[kb][0], af[kb][1], af[kb][2], af[kb][3], b2, b3);
            }
        }
        // head: p = relu(acc + bs2) . wf  (fully in-warp: warp owns all cols)
        {
            float p0 = 0.f, p1 = 0.f;
#pragma unroll
            for (int nt = 0; nt < 16; nt++) {
                float *a = acc[nt];
                int c0 = nt * 8 + 2 * (lane & 3);
                float b0 = sB2[c0], b1 = sB2[c0 + 1];
                float w0 = sWf[c0], w1 = sWf[c0 + 1];
                p0 += fmaxf(a[0] + b0, 0.f) * w0 + fmaxf(a[1] + b1, 0.f) * w1;
                p1 += fmaxf(a[2] + b0, 0.f) * w0 + fmaxf(a[3] + b1, 0.f) * w1;
            }
            p0 += __shfl_xor_sync(0xffffffffu, p0, 1);
            p0 += __shfl_xor_sync(0xffffffffu, p0, 2);
            p1 += __shfl_xor_sync(0xffffffffu, p1, 1);
            p1 += __shfl_xor_sync(0xffffffffu, p1, 2);
            if ((lane & 3) == 0) {
                float bfi = sBF[i];
                float o0 = 1.f / (1.f + __expf(-(p0 + bfi)));
                float o1 = 1.f / (1.f + __expf(-(p1 + bfi)));
                out[(size_t)(R0 + r0) * XD + i] = o0;
                out[(size_t)(R0 + r1) * XD + i] = o1;
                *(__nv_bfloat16 *)(smem + OFF_X + swz((unsigned)(r0 * 128 + i * 2))) =
                    __float2bfloat16(o0);
                *(__nv_bfloat16 *)(smem + OFF_X + swz((unsigned)(r1 * 128 + i * 2))) =
                    __float2bfloat16(o1);
            }
        }
        // next-iteration __syncthreads publishes the X column
    }
}

// ---- prep: fold adjacency mask into per-step bf16 input weights ----
__global__ void prep_A_kernel(const float *__restrict__ M, const float *__restrict__ Wi) {
    int idx = blockIdx.x * blockDim.x + threadIdx.x;
    if (idx >= XD * XD * HD) return;
    int i = idx >> 13;
    int k = (idx >> 7) & 63;
    int n = idx & 127;
    float v = (k == i) ? 0.f : M[k * XD + i] * Wi[((size_t)i * HD + n) * (XD + 1) + k];
    g_A[idx] = __float2bfloat16(v);
}

// ---- prep: transpose shared weights to [k][n] bf16 ----
__global__ void prep_W_kernel(const float *__restrict__ Ws1, const float *__restrict__ Ws2) {
    int idx = blockIdx.x * blockDim.x + threadIdx.x;
    if (idx >= HD * HD) return;
    int k = idx >> 7, n = idx & 127;
    g_W1[idx] = __float2bfloat16(Ws1[n * HD + k]);
    g_W2[idx] = __float2bfloat16(Ws2[n * HD + k]);
}

extern "C" void kernel_launch(void *const *d_in, const int *in_sizes, int n_in,
                              void *d_out, int out_size) {
    const float *x   = (const float *)d_in[0];
    const float *z   = (const float *)d_in[1];
    const float *M   = (const float *)d_in[2];
    const float *Wi  = (const float *)d_in[3];
    const float *bi  = (const float *)d_in[4];
    const float *Ws1 = (const float *)d_in[5];
    const float *bs1 = (const float *)d_in[6];
    const float *Ws2 = (const float *)d_in[7];
    const float *bs2 = (const float *)d_in[8];
    const float *wf  = (const float *)d_in[9];
    const float *bf  = (const float *)d_in[10];
    float *out = (float *)d_out;

    cudaFuncSetAttribute(gen_kernel, cudaFuncAttributeMaxDynamicSharedMemorySize,
                         (int)SMEM_BYTES);

    prep_A_kernel<<<(XD * XD * HD + 255) / 256, 256>>>(M, Wi);
    prep_W_kernel<<<(HD * HD + 255) / 256, 256>>>(Ws1, Ws2);
    gen_kernel<<<BB / BM, NT, SMEM_BYTES>>>(x, z, Wi, bi, bs1, bs2, wf, bf, out);
}